// round 16
// baseline (speedup 1.0000x reference)
#include <cuda_runtime.h>
#include <math.h>

#define IN_COUNT    256
#define OUT_COUNT   256
#define BATCH       2048
#define TB          8           // batches per block
#define ISPLIT      4           // blocks cooperating on the i-reduction
#define ITILE       (IN_COUNT / ISPLIT)   // 64 i's per block
#define N_SPLINES   5
#define N_INTERVALS 16

// Precomputed per-(o,i) parameters, transposed [i][o] for coalesced access.
__device__ float4 g_p4[IN_COUNT * OUT_COUNT];
__device__ float  g_p5[IN_COUNT * OUT_COUNT];
// Deterministic partial sums: [isplit][batch][out]  (8 MB)
__device__ float  g_partial[ISPLIT * BATCH * OUT_COUNT];

__device__ __forceinline__ float ex2f_(float x) {
    float r; asm("ex2.approx.ftz.f32 %0, %1;" : "=f"(r) : "f"(x)); return r;
}
__device__ __forceinline__ float lg2f_(float x) {
    float r; asm("lg2.approx.ftz.f32 %0, %1;" : "=f"(r) : "f"(x)); return r;
}

// Fast log2 for z >= 1 (z in [1, ~22]) on the FMA/ALU pipes (no MUFU).
// Branch-free sqrt(2)-centered frexp: the integer add carries into the
// exponent field exactly when mantissa(z) >= sqrt(2), so the renormalized
// mantissa m lands in [0.707, 1.414), f = m-1 in [-0.293, 0.414].
// Degree-8 Taylor for log2(1+f): |err| <= ~1e-4 log2-units worst case;
// ~4e-5 relative in the output — >=20x under the 1e-3 gate. z=1 -> exactly 0.
__device__ __forceinline__ float fast_lg2_ge1(float z) {
    int   iz = __float_as_int(z);
    int   biased = iz + (0x00800000 - 0x003504F3);     // 0x3504F3 = frac(sqrt2)
    int   ez = (biased >> 23) - 127;
    float m  = __int_as_float(iz - (ez << 23));        // [0.707, 1.414)
    float f  = m - 1.0f;
    // P(f) ~= log2(1+f)/f  (Taylor coeffs * log2(e))
    float p = -0.180336880f;
    p = fmaf(p, f,  0.206099291f);
    p = fmaf(p, f, -0.240449173f);
    p = fmaf(p, f,  0.288539008f);
    p = fmaf(p, f, -0.360673760f);
    p = fmaf(p, f,  0.480898347f);
    p = fmaf(p, f, -0.721347520f);
    p = fmaf(p, f,  1.442695041f);
    return fmaf(f, p, (float)ez);
}

// ---------------------------------------------------------------------------
// Kernel 1: spline eval + constant folding. breaks/coefs staged in shared.
// FIX (R13): s_cf has 320 entries > 256 threads — grid-stride the staging
// loops so every entry is written (previous version left spline 4's coefs
// uninitialized -> rel_err 0.203).
// ---------------------------------------------------------------------------
__global__ __launch_bounds__(256) void KAN_precompute_kernel(
        const float* __restrict__ w,
        const float* __restrict__ raw_gamma,
        const float* __restrict__ breaks,
        const float* __restrict__ coefs,
        const float* __restrict__ mu_p,
        const float* __restrict__ sigma_p)
{
    __shared__ float s_br[N_SPLINES * (N_INTERVALS + 1)];   // 85
    __shared__ float s_cf[N_SPLINES * N_INTERVALS * 4];     // 320

    for (int idx = threadIdx.x; idx < N_SPLINES * (N_INTERVALS + 1); idx += 256)
        s_br[idx] = breaks[idx];
    for (int idx = threadIdx.x; idx < N_SPLINES * N_INTERVALS * 4; idx += 256)
        s_cf[idx] = coefs[idx];
    __syncthreads();

    int e = blockIdx.x * blockDim.x + threadIdx.x;
    if (e >= IN_COUNT * OUT_COUNT) return;
    int o = e >> 8;
    int i = e & 255;

    float mu = *mu_p, sigma = *sigma_p;
    float wv = w[e];
    float wn = (fminf(fmaxf(wv, 5.5f), 35.5f) - mu) / sigma;

    float b[N_SPLINES];
    #pragma unroll
    for (int s = 0; s < N_SPLINES; ++s) {
        const float* br = s_br + s * (N_INTERVALS + 1);
        float wc = fminf(fmaxf(wn, br[0]), br[N_INTERVALS] - 1e-6f);
        int idx = 0;
        #pragma unroll
        for (int k = 1; k <= N_INTERVALS; ++k) idx += (wc >= br[k]) ? 1 : 0;
        if (idx > N_INTERVALS - 1) idx = N_INTERVALS - 1;
        const float* a = s_cf + (s * N_INTERVALS + idx) * 4;
        float t = wc - br[idx];
        b[s] = ((a[0] * t + a[1]) * t + a[2]) * t + a[3];
    }

    float rg = raw_gamma[e];
    float g = (fmaxf(rg, 0.0f) + log1pf(expf(-fabsf(rg)))) * (1.0f / OUT_COUNT);

    const float LOG2E = 1.4426950408889634f;
    const float LN2   = 0.6931471805599453f;

    float4 P;
    P.x = b[2] * LOG2E;        // C3
    P.y = b[3];                // C4
    P.z = b[1] * LN2;          // C2
    P.w = b[0] * g * LN2;      // CA
    int te = i * OUT_COUNT + o;
    g_p4[te] = P;
    g_p5[te] = b[4] * g;       // C5
}

// ---------------------------------------------------------------------------
// Kernel 2: main compute. blockIdx.x = batch tile, blockIdx.y = i-split.
// 4 MUFU + ~16 FMA per active element: both pipes balanced (~114K chip-cyc).
// ---------------------------------------------------------------------------
__global__ __launch_bounds__(256) void KAN_main_kernel(
        const float* __restrict__ x)
{
    __shared__ float xs[TB][ITILE];

    const int o  = threadIdx.x;
    const int b0 = blockIdx.x * TB;
    const int i0 = blockIdx.y * ITILE;

    for (int idx = threadIdx.x; idx < TB * ITILE; idx += 256) {
        int t = idx / ITILE, i = idx % ITILE;
        xs[t][i] = fmaxf(x[(b0 + t) * IN_COUNT + i0 + i], 0.0f);
    }
    __syncthreads();

    float acc[TB];
    #pragma unroll
    for (int t = 0; t < TB; ++t) acc[t] = 0.0f;

    const float4* __restrict__ p4 = g_p4 + i0 * OUT_COUNT + o;
    const float*  __restrict__ p5 = g_p5 + i0 * OUT_COUNT + o;

    float4 P  = p4[0];
    float  c5 = p5[0];

    for (int i = 0; i < ITILE; ++i) {
        int inx = (i + 1 < ITILE) ? (i + 1) : i;
        float4 Pn  = p4[inx * OUT_COUNT];
        float  c5n = p5[inx * OUT_COUNT];

        #pragma unroll
        for (int t = 0; t < TB; ++t) {
            float xv = xs[t][i];
            if (xv > 0.0f) {                       // warp-uniform skip
                float e    = ex2f_(P.x * xv);               // 2^{C3 x}     [MUFU]
                float base = e - 1.0f;
                float p    = ex2f_(P.y * lg2f_(base));      // base^{b4}    [MUFU x2]
                float t2   = lg2f_(1.0f + p);               //              [MUFU]
                float z    = fmaf(P.z, t2, 1.0f);           // z >= 1
                float u2   = fast_lg2_ge1(z);               //              [FMA/ALU]
                acc[t] = fmaf(P.w, u2, fmaf(c5, xv, acc[t]));
            }
        }
        P  = Pn;
        c5 = c5n;
    }

    float* dst = g_partial + (size_t)blockIdx.y * (BATCH * OUT_COUNT)
                 + b0 * OUT_COUNT + o;
    #pragma unroll
    for (int t = 0; t < TB; ++t)
        dst[t * OUT_COUNT] = acc[t];
}

// ---------------------------------------------------------------------------
// Kernel 3: combine ISPLIT partials + final softplus (float4 vectorized).
// ---------------------------------------------------------------------------
__global__ __launch_bounds__(256) void KAN_combine_kernel(float4* __restrict__ out)
{
    int idx = blockIdx.x * blockDim.x + threadIdx.x;
    if (idx >= (BATCH * OUT_COUNT) / 4) return;
    const float4* p = (const float4*)g_partial;
    float4 y = p[idx];
    #pragma unroll
    for (int s = 1; s < ISPLIT; ++s) {
        float4 v = p[s * (BATCH * OUT_COUNT / 4) + idx];
        y.x += v.x; y.y += v.y; y.z += v.z; y.w += v.w;
    }
    float4 r;
    r.x = fmaxf(y.x, 0.0f) + log1pf(expf(-fabsf(y.x)));
    r.y = fmaxf(y.y, 0.0f) + log1pf(expf(-fabsf(y.y)));
    r.z = fmaxf(y.z, 0.0f) + log1pf(expf(-fabsf(y.z)));
    r.w = fmaxf(y.w, 0.0f) + log1pf(expf(-fabsf(y.w)));
    out[idx] = r;
}

// ---------------------------------------------------------------------------
// Inputs: x, w, raw_gamma, breaks, coefs, mu, sigma. Output fp32 [B, O].
// ---------------------------------------------------------------------------
extern "C" void kernel_launch(void* const* d_in, const int* in_sizes, int n_in,
                              void* d_out, int out_size)
{
    const float* x      = (const float*)d_in[0];
    const float* w      = (const float*)d_in[1];
    const float* rgam   = (const float*)d_in[2];
    const float* breaks = (const float*)d_in[3];
    const float* coefs  = (const float*)d_in[4];
    const float* mu     = (const float*)d_in[5];
    const float* sigma  = (const float*)d_in[6];

    KAN_precompute_kernel<<<(IN_COUNT * OUT_COUNT + 255) / 256, 256>>>(
        w, rgam, breaks, coefs, mu, sigma);

    dim3 grid(BATCH / TB, ISPLIT);
    KAN_main_kernel<<<grid, 256>>>(x);

    KAN_combine_kernel<<<(BATCH * OUT_COUNT / 4 + 255) / 256, 256>>>(
        (float4*)d_out);
}